// round 2
// baseline (speedup 1.0000x reference)
#include <cuda_runtime.h>
#include <math.h>

#define B    8
#define S    256
#define H    768
#define P    256
#define NE   20000
#define NT   100000
#define NR   200
#define HOPS 3

// ---------------- scratch (device globals; no allocation) ----------------
__device__ float g_wvp[H];
__device__ float g_D[B * H];
__device__ float g_R[B * HOPS * NR];
__device__ float g_CS[B * HOPS * 2];
__device__ float g_walked[B * NE];
__device__ float g_walk[B * HOPS * NE];
__device__ float g_sums[B];
__device__ float g_LD[B * H];
__device__ float g_scores[B * NE];

// ---------------- helpers ----------------
__device__ __forceinline__ float warpSum(float v) {
    #pragma unroll
    for (int o = 16; o; o >>= 1) v += __shfl_xor_sync(0xffffffffu, v, o);
    return v;
}
__device__ __forceinline__ float warpMax(float v) {
    #pragma unroll
    for (int o = 16; o; o >>= 1) v = fmaxf(v, __shfl_xor_sync(0xffffffffu, v, o));
    return v;
}

// ---------------- kernels ----------------

// zero g_walked; warps 0..767 also compute wvp[h] = sum_p W_v[h,p]*W_p[p]
__global__ void k_init(const float* __restrict__ Wv, const float* __restrict__ Wp) {
    int idx = blockIdx.x * blockDim.x + threadIdx.x;
    if (idx < B * NE) g_walked[idx] = 0.f;
    int warp = idx >> 5;
    int lane = threadIdx.x & 31;
    if (warp < H) {
        float acc = 0.f;
        #pragma unroll
        for (int p = lane; p < P; p += 32) acc += Wv[warp * P + p] * Wp[p];
        acc = warpSum(acc);
        if (lane == 0) g_wvp[warp] = acc;
    }
}

// per-b: logits over s, softmax, D[b,h] = sum_s p[s]*mask[b,s]*lhs[b,s,h]
// block per b, 1024 threads
__global__ void k_Dall(const float* __restrict__ lhs, const float* __restrict__ mask) {
    int b = blockIdx.x;
    int tid = threadIdx.x;
    int lane = tid & 31, wid = tid >> 5;   // 32 warps
    __shared__ float sw[H];
    __shared__ float sl[S];
    __shared__ float red[32];

    for (int i = tid; i < H; i += 1024) sw[i] = g_wvp[i];
    __syncthreads();

    // each warp computes 8 logits
    #pragma unroll
    for (int k = 0; k < 8; k++) {
        int s = wid * 8 + k;
        const float* r = lhs + ((size_t)b * S + s) * H;
        float acc = 0.f;
        #pragma unroll
        for (int h = lane; h < H; h += 32) acc += r[h] * sw[h];
        acc = warpSum(acc);
        if (lane == 0) sl[s] = acc;
    }
    __syncthreads();

    // softmax over 256
    float v = (tid < S) ? sl[tid] : -INFINITY;
    float m = warpMax(v);
    if (lane == 0) red[wid] = m;
    __syncthreads();
    if (tid < 32) { float x = red[tid]; x = warpMax(x); if (tid == 0) red[0] = x; }
    __syncthreads();
    float mx = red[0];
    __syncthreads();
    float e = (tid < S) ? expf(v - mx) : 0.f;
    float ssum = warpSum(e);
    if (lane == 0) red[wid] = ssum;
    __syncthreads();
    if (tid < 32) { float x = red[tid]; x = warpSum(x); if (tid == 0) red[0] = x; }
    __syncthreads();
    float inv = 1.f / red[0];
    if (tid < S) sl[tid] = e * inv * mask[b * S + tid];
    __syncthreads();

    // weighted sum: thread per h column
    if (tid < H) {
        float a = 0.f;
        const float* base = lhs + (size_t)b * S * H + tid;
        #pragma unroll 4
        for (int s = 0; s < S; s++) a += sl[s] * base[(size_t)s * H];
        g_D[b * H + tid] = a;
    }
}

// rels_seq softmax (200-wide) and checks_seq softmax (2-wide), block per (b,hop)
__global__ void k_rels(const float* __restrict__ Wr, const float* __restrict__ Wc) {
    int b = blockIdx.x / HOPS, hop = blockIdx.x % HOPS;
    int tid = threadIdx.x;              // 256
    int lane = tid & 31, wid = tid >> 5;
    __shared__ float sD[H];
    __shared__ float sm[NR];
    __shared__ float scv[2];
    __shared__ float red[8];
    for (int i = tid; i < H; i += 256) sD[i] = g_D[b * H + i];
    __syncthreads();

    if (tid < NR) {
        float acc = 0.f;
        #pragma unroll 4
        for (int h = 0; h < H; h++) acc += sD[h] * Wr[h * (HOPS * NR) + hop * NR + tid];
        sm[tid] = acc;
    }
    if (tid >= 200 && tid < 202) {
        int c = tid - 200;
        float acc = 0.f;
        for (int h = 0; h < H; h++) acc += sD[h] * Wc[h * (HOPS * 2) + hop * 2 + c];
        scv[c] = acc;
    }
    __syncthreads();

    float v = (tid < NR) ? sm[tid] : -INFINITY;
    float m = warpMax(v);
    if (lane == 0) red[wid] = m;
    __syncthreads();
    if (tid == 0) {
        float mm = red[0];
        #pragma unroll
        for (int i = 1; i < 8; i++) mm = fmaxf(mm, red[i]);
        red[0] = mm;
    }
    __syncthreads();
    float mx = red[0];
    __syncthreads();
    float e = (tid < NR) ? expf(sm[tid] - mx) : 0.f;
    float s = warpSum(e);
    if (lane == 0) red[wid] = s;
    __syncthreads();
    if (tid == 0) {
        float ss = 0.f;
        #pragma unroll
        for (int i = 0; i < 8; i++) ss += red[i];
        red[0] = ss;
    }
    __syncthreads();
    if (tid < NR) g_R[(b * HOPS + hop) * NR + tid] = e / red[0];

    if (tid == 0) {
        float c0 = scv[0], c1 = scv[1];
        float m2 = fmaxf(c0, c1);
        float e0 = expf(c0 - m2), e1 = expf(c1 - m2);
        float inv = 1.f / (e0 + e1);
        g_CS[(b * HOPS + hop) * 2 + 0] = e0 * inv;
        g_CS[(b * HOPS + hop) * 2 + 1] = e1 * inv;
    }
}

// one hop: trip = R[b,hop,rel] * e_prev[head]; atomic scatter by tail
__global__ void k_scatter(int hop, const float* __restrict__ init_ent,
                          const int* __restrict__ heads,
                          const int* __restrict__ rels,
                          const int* __restrict__ tails) {
    int idx = blockIdx.x * blockDim.x + threadIdx.x;
    if (idx >= B * NT) return;
    int b = idx / NT;
    int h = heads[idx];
    int r = rels[idx];
    int t = tails[idx];
    const float* esrc = (hop == 0) ? (init_ent + b * NE)
                                   : (g_walk + (size_t)(b * HOPS + hop - 1) * NE);
    float trip = g_R[(b * HOPS + hop) * NR + r] * esrc[h];
    atomicAdd(&g_walked[b * NE + t], trip);
}

// LD[b,chunk*128 + tid] ; grid = B*6 blocks of 128
__global__ void k_LD(const float* __restrict__ Lw) {
    int b = blockIdx.x / 6;
    int chunk = blockIdx.x % 6;
    int tid = threadIdx.x;  // 128
    __shared__ float sD[H];
    for (int i = tid; i < H; i += 128) sD[i] = g_D[b * H + i];
    __syncthreads();
    int c = chunk * 128 + tid;
    float a = 0.f;
    #pragma unroll 4
    for (int h = 0; h < H; h++) a += sD[h] * Lw[(size_t)h * H + c];
    g_LD[b * H + c] = a;
}

// scores[b,e] = LD[b,:] . sum_t EE[e,t,:]    (warp per e, t-reduced first)
__global__ void k_scores(const float* __restrict__ EE) {
    __shared__ float4 sLD[B * 192];     // 24 KB
    const float4* LD4 = (const float4*)g_LD;
    for (int i = threadIdx.x; i < B * 192; i += blockDim.x) sLD[i] = LD4[i];
    __syncthreads();
    int warp = threadIdx.x >> 5, lane = threadIdx.x & 31;
    int e = blockIdx.x * 8 + warp;
    if (e >= NE) return;
    const float4* base = (const float4*)(EE + (size_t)e * 3072);
    float acc[B];
    #pragma unroll
    for (int b = 0; b < B; b++) acc[b] = 0.f;
    #pragma unroll
    for (int it = 0; it < 6; it++) {
        int j = lane + it * 32;
        float4 v0 = base[j], v1 = base[j + 192], v2 = base[j + 384], v3 = base[j + 576];
        float4 sx;
        sx.x = v0.x + v1.x + v2.x + v3.x;
        sx.y = v0.y + v1.y + v2.y + v3.y;
        sx.z = v0.z + v1.z + v2.z + v3.z;
        sx.w = v0.w + v1.w + v2.w + v3.w;
        #pragma unroll
        for (int b = 0; b < B; b++) {
            float4 l = sLD[b * 192 + j];
            acc[b] += sx.x * l.x + sx.y * l.y + sx.z * l.z + sx.w * l.w;
        }
    }
    #pragma unroll
    for (int b = 0; b < B; b++) {
        float v = warpSum(acc[b]);
        if (lane == 0) g_scores[b * NE + e] = v;
    }
}

// per-b sum of walked
__global__ void k_sum() {
    int b = blockIdx.x;
    int tid = threadIdx.x;  // 1024
    int lane = tid & 31, wid = tid >> 5;
    __shared__ float red[32];
    float s = 0.f;
    for (int e = tid; e < NE; e += 1024) s += g_walked[b * NE + e];
    s = warpSum(s);
    if (lane == 0) red[wid] = s;
    __syncthreads();
    if (tid < 32) {
        float v = red[tid];
        v = warpSum(v);
        if (tid == 0) g_sums[b] = v;
    }
}

// normalize into g_walk[b,hop,:], re-zero g_walked for next hop
__global__ void k_norm(int hop) {
    int i = blockIdx.x * blockDim.x + threadIdx.x;
    if (i >= B * NE) return;
    int b = i / NE;
    int e = i - b * NE;
    float v = g_walked[i];
    g_walk[(size_t)(b * HOPS + hop) * NE + e] = v / (g_sums[b] + 1e-6f);
    g_walked[i] = 0.f;
}

// checks softmax over NE + final combine, block per (b,hop)
__global__ void k_final(float* __restrict__ out) {
    int bh = blockIdx.x;
    int b = bh / HOPS;
    const float* w  = g_walk   + (size_t)bh * NE;
    const float* sc = g_scores + (size_t)b * NE;
    int tid = threadIdx.x;   // 1024
    int lane = tid & 31, wid = tid >> 5;
    __shared__ float red[32];
    __shared__ float sbc;

    float m = -INFINITY;
    for (int e = tid; e < NE; e += 1024) m = fmaxf(m, w[e] * sc[e]);
    m = warpMax(m);
    if (lane == 0) red[wid] = m;
    __syncthreads();
    if (tid < 32) {
        float v = red[tid];
        v = warpMax(v);
        if (tid == 0) sbc = v;
    }
    __syncthreads();
    float mx = sbc;
    __syncthreads();

    float s = 0.f;
    for (int e = tid; e < NE; e += 1024) s += expf(w[e] * sc[e] - mx);
    s = warpSum(s);
    if (lane == 0) red[wid] = s;
    __syncthreads();
    if (tid < 32) {
        float v = red[tid];
        v = warpSum(v);
        if (tid == 0) sbc = v;
    }
    __syncthreads();
    float inv = 1.f / sbc;
    float c0 = g_CS[bh * 2 + 0];
    float c1 = g_CS[bh * 2 + 1];
    for (int e = tid; e < NE; e += 1024) {
        float we = w[e];
        out[(size_t)bh * NE + e] = c0 * we + c1 * expf(we * sc[e] - mx) * inv;
    }
}

// ---------------- launcher ----------------
extern "C" void kernel_launch(void* const* d_in, const int* in_sizes, int n_in,
                              void* d_out, int out_size) {
    const float* lhs      = (const float*)d_in[0];   // (B,S,H)
    const float* mask     = (const float*)d_in[1];   // (B,S)
    const float* init_ent = (const float*)d_in[2];   // (B,NE)
    const float* EE       = (const float*)d_in[3];   // (NE,4,H)
    // d_in[4] = W_q  (eliminated: constant term cancels in pointer softmax)
    const float* Wv       = (const float*)d_in[5];   // (H,P)
    const float* Wp       = (const float*)d_in[6];   // (P,1)
    const float* Wr       = (const float*)d_in[7];   // (H, HOPS*NR)
    const float* Wc       = (const float*)d_in[8];   // (H, HOPS*2)
    const float* Lw       = (const float*)d_in[9];   // (H,H)
    const int*   heads    = (const int*)d_in[10];    // (B,NT)
    const int*   rels     = (const int*)d_in[11];
    const int*   tails    = (const int*)d_in[12];
    float* out = (float*)d_out;                      // (B,HOPS,NE)

    // Launch order chosen so the ncu capture slot (4th..6th launch) lands on
    // k_scatter / k_scores — the unattributed heavy kernels.
    k_init   <<<625, 256>>>(Wv, Wp);                                   // 1
    k_Dall   <<<B, 1024>>>(lhs, mask);                                 // 2
    k_rels   <<<B * HOPS, 256>>>(Wr, Wc);                              // 3
    k_scatter<<<(B * NT + 255) / 256, 256>>>(0, init_ent, heads, rels, tails); // 4
    k_LD     <<<B * 6, 128>>>(Lw);                                     // 5
    k_scores <<<NE / 8, 256>>>(EE);                                    // 6
    k_sum    <<<B, 1024>>>();                                          // 7
    k_norm   <<<625, 256>>>(0);                                        // 8
    for (int hop = 1; hop < HOPS; hop++) {
        k_scatter<<<(B * NT + 255) / 256, 256>>>(hop, init_ent, heads, rels, tails);
        k_sum    <<<B, 1024>>>();
        k_norm   <<<625, 256>>>(hop);
    }
    k_final  <<<B * HOPS, 1024>>>(out);
}

// round 3
// speedup vs baseline: 2.6365x; 2.6365x over previous
#include <cuda_runtime.h>
#include <math.h>

#define B    8
#define S    256
#define H    768
#define P    256
#define NE   20000
#define NT   100000
#define NR   200
#define HOPS 3

// ---------------- scratch (device globals) ----------------
__device__ float g_wvp[H];
__device__ float g_slogit[B * S];
__device__ float g_ptr[B * S];                 // softmax(pointers)*mask
__device__ float g_D[B * H];
__device__ float g_Rlog[B * HOPS * NR];        // rels logits (atomic acc)
__device__ float g_Clog[B * HOPS * 2];         // checks logits (atomic acc)
__device__ float g_R[B * HOPS * NR];
__device__ float g_CS[B * HOPS * 2];
__device__ float g_LD[B * H];                  // atomic acc
__device__ float g_walkraw[B * HOPS * NE];     // raw segment sums per hop
__device__ float g_inv[B * HOPS];              // 1/(sum+1e-6) per (b,hop)
__device__ float g_scores[B * NE];

// ---------------- helpers ----------------
__device__ __forceinline__ float warpSum(float v) {
    #pragma unroll
    for (int o = 16; o; o >>= 1) v += __shfl_xor_sync(0xffffffffu, v, o);
    return v;
}
__device__ __forceinline__ float warpMax(float v) {
    #pragma unroll
    for (int o = 16; o; o >>= 1) v = fmaxf(v, __shfl_xor_sync(0xffffffffu, v, o));
    return v;
}

// ---------------- kernels ----------------

// zero all atomic-accumulated scratch; first 768 warps also compute wvp
__global__ void k_init(const float* __restrict__ Wv, const float* __restrict__ Wp) {
    int idx = blockIdx.x * blockDim.x + threadIdx.x;          // 1875*256 = 480000
    if (idx < B * HOPS * NE) g_walkraw[idx] = 0.f;
    if (idx < B * H) { g_D[idx] = 0.f; g_LD[idx] = 0.f; }
    if (idx < B * HOPS * NR) g_Rlog[idx] = 0.f;
    if (idx < B * HOPS * 2) g_Clog[idx] = 0.f;
    int warp = idx >> 5;
    int lane = threadIdx.x & 31;
    if (warp < H) {
        float acc = 0.f;
        #pragma unroll
        for (int p = lane; p < P; p += 32) acc += Wv[warp * P + p] * Wp[p];
        acc = warpSum(acc);
        if (lane == 0) g_wvp[warp] = acc;
    }
}

// slogit[b,s] = dot(lhs[b,s,:], wvp) — warp per row, 2048 warps
__global__ void k_logit(const float* __restrict__ lhs) {
    __shared__ float4 sw[H / 4];
    for (int i = threadIdx.x; i < H / 4; i += blockDim.x)
        sw[i] = ((const float4*)g_wvp)[i];
    __syncthreads();
    int warp = threadIdx.x >> 5, lane = threadIdx.x & 31;
    int row = blockIdx.x * 32 + warp;           // 64 blocks * 32 warps = 2048
    const float4* base = (const float4*)(lhs + (size_t)row * H);
    float acc = 0.f;
    #pragma unroll
    for (int it = 0; it < 6; it++) {
        int j = lane + it * 32;
        float4 v = base[j], w = sw[j];
        acc += v.x * w.x + v.y * w.y + v.z * w.z + v.w * w.w;
    }
    acc = warpSum(acc);
    if (lane == 0) g_slogit[row] = acc;
}

// softmax over S per b, apply mask -> g_ptr
__global__ void k_smax(const float* __restrict__ mask) {
    int b = blockIdx.x;
    int tid = threadIdx.x;     // 256
    int lane = tid & 31, wid = tid >> 5;
    __shared__ float red[8];
    float l = g_slogit[b * S + tid];
    float m = warpMax(l);
    if (lane == 0) red[wid] = m;
    __syncthreads();
    if (tid == 0) {
        float mm = red[0];
        #pragma unroll
        for (int i = 1; i < 8; i++) mm = fmaxf(mm, red[i]);
        red[0] = mm;
    }
    __syncthreads();
    float mx = red[0];
    __syncthreads();
    float e = expf(l - mx);
    float s = warpSum(e);
    if (lane == 0) red[wid] = s;
    __syncthreads();
    if (tid == 0) {
        float ss = 0.f;
        #pragma unroll
        for (int i = 0; i < 8; i++) ss += red[i];
        red[0] = ss;
    }
    __syncthreads();
    g_ptr[b * S + tid] = e / red[0] * mask[b * S + tid];
}

// D[b,h] += sum_{s in chunk} ptr[b,s]*lhs[b,s,h]
// grid (6 h-tiles, 4 s-chunks, B), 128 threads
__global__ void k_D(const float* __restrict__ lhs) {
    int ht = blockIdx.x, sc = blockIdx.y, b = blockIdx.z;
    int tid = threadIdx.x;
    __shared__ float sp[64];
    if (tid < 64) sp[tid] = g_ptr[b * S + sc * 64 + tid];
    __syncthreads();
    int col = ht * 128 + tid;
    const float* base = lhs + ((size_t)(b * S + sc * 64)) * H + col;
    float a = 0.f;
    #pragma unroll 8
    for (int s = 0; s < 64; s++) a += sp[s] * base[(size_t)s * H];
    atomicAdd(&g_D[b * H + col], a);
}

// fused partial GEMVs: D @ Wr (->Rlog), D @ Wc (->Clog), D @ Lw (->LD)
// grid (12 col-tiles, 4 h-chunks, B), 128 threads
__global__ void k_lin(const float* __restrict__ Wr, const float* __restrict__ Wc,
                      const float* __restrict__ Lw) {
    int tile = blockIdx.x, hc = blockIdx.y, b = blockIdx.z;
    int tid = threadIdx.x;
    int h0 = hc * 192;
    __shared__ float sD[192];
    if (tid < 128) sD[tid] = g_D[b * H + h0 + tid];
    if (tid < 64)  sD[128 + tid] = g_D[b * H + h0 + 128 + tid];
    __syncthreads();

    const float* W;
    float* dst;
    int ncols, col0, stride;
    if (tile < 5)       { W = Wr; dst = g_Rlog + b * (HOPS * NR); ncols = HOPS * NR; col0 = tile * 128;      stride = HOPS * NR; }
    else if (tile == 5) { W = Wc; dst = g_Clog + b * (HOPS * 2);  ncols = HOPS * 2;  col0 = 0;               stride = HOPS * 2; }
    else                { W = Lw; dst = g_LD   + b * H;           ncols = H;         col0 = (tile - 6) * 128; stride = H; }

    int col = col0 + tid;
    if (col >= ncols) return;
    const float* w = W + (size_t)h0 * stride + col;
    float acc = 0.f;
    #pragma unroll 8
    for (int h = 0; h < 192; h++) acc += sD[h] * w[(size_t)h * stride];
    atomicAdd(&dst[col], acc);
}

// softmax rels (200) + checks (2) per (b,hop)
__global__ void k_rsm() {
    int bh = blockIdx.x;
    int tid = threadIdx.x;   // 256
    int lane = tid & 31, wid = tid >> 5;
    __shared__ float red[8];
    float v = (tid < NR) ? g_Rlog[bh * NR + tid] : -INFINITY;
    float m = warpMax(v);
    if (lane == 0) red[wid] = m;
    __syncthreads();
    if (tid == 0) {
        float mm = red[0];
        #pragma unroll
        for (int i = 1; i < 8; i++) mm = fmaxf(mm, red[i]);
        red[0] = mm;
    }
    __syncthreads();
    float mx = red[0];
    __syncthreads();
    float e = (tid < NR) ? expf(v - mx) : 0.f;
    float s = warpSum(e);
    if (lane == 0) red[wid] = s;
    __syncthreads();
    if (tid == 0) {
        float ss = 0.f;
        #pragma unroll
        for (int i = 0; i < 8; i++) ss += red[i];
        red[0] = ss;
    }
    __syncthreads();
    if (tid < NR) g_R[bh * NR + tid] = e / red[0];
    if (tid == 0) {
        float c0 = g_Clog[bh * 2 + 0], c1 = g_Clog[bh * 2 + 1];
        float m2 = fmaxf(c0, c1);
        float e0 = expf(c0 - m2), e1 = expf(c1 - m2);
        float inv = 1.f / (e0 + e1);
        g_CS[bh * 2 + 0] = e0 * inv;
        g_CS[bh * 2 + 1] = e1 * inv;
    }
}

// scores[b,e] = LD[b,:] . sum_t EE[e,t,:]   (warp per e)
__global__ void k_scores(const float* __restrict__ EE) {
    __shared__ float4 sLD[B * 192];     // 24 KB
    const float4* LD4 = (const float4*)g_LD;
    for (int i = threadIdx.x; i < B * 192; i += blockDim.x) sLD[i] = LD4[i];
    __syncthreads();
    int warp = threadIdx.x >> 5, lane = threadIdx.x & 31;
    int e = blockIdx.x * 8 + warp;
    if (e >= NE) return;
    const float4* base = (const float4*)(EE + (size_t)e * 3072);
    float acc[B];
    #pragma unroll
    for (int b = 0; b < B; b++) acc[b] = 0.f;
    #pragma unroll
    for (int it = 0; it < 6; it++) {
        int j = lane + it * 32;
        float4 v0 = base[j], v1 = base[j + 192], v2 = base[j + 384], v3 = base[j + 576];
        float4 sx;
        sx.x = v0.x + v1.x + v2.x + v3.x;
        sx.y = v0.y + v1.y + v2.y + v3.y;
        sx.z = v0.z + v1.z + v2.z + v3.z;
        sx.w = v0.w + v1.w + v2.w + v3.w;
        #pragma unroll
        for (int b = 0; b < B; b++) {
            float4 l = sLD[b * 192 + j];
            acc[b] += sx.x * l.x + sx.y * l.y + sx.z * l.z + sx.w * l.w;
        }
    }
    #pragma unroll
    for (int b = 0; b < B; b++) {
        float v = warpSum(acc[b]);
        if (lane == 0) g_scores[b * NE + e] = v;
    }
}

// one hop: trip = R[b,hop,rel] * prev[head]; scatter-add by tail into walkraw[hop]
__global__ void k_scatter(int hop, const float* __restrict__ init_ent,
                          const int* __restrict__ heads,
                          const int* __restrict__ rels,
                          const int* __restrict__ tails) {
    int idx = blockIdx.x * blockDim.x + threadIdx.x;
    if (idx >= B * NT) return;
    int b = idx / NT;
    int h = heads[idx];
    int r = rels[idx];
    int t = tails[idx];
    float prev;
    if (hop == 0) {
        prev = init_ent[b * NE + h];
    } else {
        prev = g_walkraw[(size_t)(b * HOPS + hop - 1) * NE + h] * g_inv[b * HOPS + hop - 1];
    }
    float trip = g_R[(b * HOPS + hop) * NR + r] * prev;
    atomicAdd(&g_walkraw[(size_t)(b * HOPS + hop) * NE + t], trip);
}

// per-(b,hop) sum of walkraw -> g_inv
__global__ void k_sum(int hop) {
    int b = blockIdx.x;
    int tid = threadIdx.x;  // 1024
    int lane = tid & 31, wid = tid >> 5;
    __shared__ float red[32];
    const float* w = g_walkraw + (size_t)(b * HOPS + hop) * NE;
    float s = 0.f;
    for (int e = tid; e < NE; e += 1024) s += w[e];
    s = warpSum(s);
    if (lane == 0) red[wid] = s;
    __syncthreads();
    if (tid < 32) {
        float v = red[tid];
        v = warpSum(v);
        if (tid == 0) g_inv[b * HOPS + hop] = 1.f / (v + 1e-6f);
    }
}

// checks softmax over NE + combine, block per (b,hop)
__global__ void k_final(float* __restrict__ out) {
    int bh = blockIdx.x;
    int b = bh / HOPS;
    const float* wr = g_walkraw + (size_t)bh * NE;
    const float* sc = g_scores + (size_t)b * NE;
    float winv = g_inv[bh];
    int tid = threadIdx.x;   // 1024
    int lane = tid & 31, wid = tid >> 5;
    __shared__ float red[32];
    __shared__ float sbc;

    float m = -INFINITY;
    for (int e = tid; e < NE; e += 1024) m = fmaxf(m, wr[e] * winv * sc[e]);
    m = warpMax(m);
    if (lane == 0) red[wid] = m;
    __syncthreads();
    if (tid < 32) {
        float v = red[tid];
        v = warpMax(v);
        if (tid == 0) sbc = v;
    }
    __syncthreads();
    float mx = sbc;
    __syncthreads();

    float s = 0.f;
    for (int e = tid; e < NE; e += 1024) s += expf(wr[e] * winv * sc[e] - mx);
    s = warpSum(s);
    if (lane == 0) red[wid] = s;
    __syncthreads();
    if (tid < 32) {
        float v = red[tid];
        v = warpSum(v);
        if (tid == 0) sbc = v;
    }
    __syncthreads();
    float inv = 1.f / sbc;
    float c0 = g_CS[bh * 2 + 0];
    float c1 = g_CS[bh * 2 + 1];
    for (int e = tid; e < NE; e += 1024) {
        float we = wr[e] * winv;
        out[(size_t)bh * NE + e] = c0 * we + c1 * expf(we * sc[e] - mx) * inv;
    }
}

// ---------------- launcher ----------------
extern "C" void kernel_launch(void* const* d_in, const int* in_sizes, int n_in,
                              void* d_out, int out_size) {
    const float* lhs      = (const float*)d_in[0];   // (B,S,H)
    const float* mask     = (const float*)d_in[1];   // (B,S)
    const float* init_ent = (const float*)d_in[2];   // (B,NE)
    const float* EE       = (const float*)d_in[3];   // (NE,4,H)
    // d_in[4] = W_q  (eliminated: constant term cancels in pointer softmax)
    const float* Wv       = (const float*)d_in[5];   // (H,P)
    const float* Wp       = (const float*)d_in[6];   // (P,1)
    const float* Wr       = (const float*)d_in[7];   // (H, HOPS*NR)
    const float* Wc       = (const float*)d_in[8];   // (H, HOPS*2)
    const float* Lw       = (const float*)d_in[9];   // (H,H)
    const int*   heads    = (const int*)d_in[10];    // (B,NT)
    const int*   rels     = (const int*)d_in[11];
    const int*   tails    = (const int*)d_in[12];
    float* out = (float*)d_out;                      // (B,HOPS,NE)

    k_init  <<<1875, 256>>>(Wv, Wp);                 // 1
    k_logit <<<64, 1024>>>(lhs);                     // 2
    k_smax  <<<B, 256>>>(mask);                      // 3
    { dim3 g(6, 4, B);  k_D   <<<g, 128>>>(lhs); }   // 4  (profiled slot)
    { dim3 g(12, 4, B); k_lin <<<g, 128>>>(Wr, Wc, Lw); } // 5
    k_rsm   <<<B * HOPS, 256>>>();                   // 6
    k_scores<<<NE / 8, 256>>>(EE);                   // 7
    for (int hop = 0; hop < HOPS; hop++) {
        k_scatter<<<(B * NT + 255) / 256, 256>>>(hop, init_ent, heads, rels, tails);
        k_sum    <<<B, 1024>>>(hop);
    }
    k_final <<<B * HOPS, 1024>>>(out);
}